// round 3
// baseline (speedup 1.0000x reference)
#include <cuda_runtime.h>

// ---------------------------------------------------------------------------
// Problem constants
// ---------------------------------------------------------------------------
constexpr int TFR   = 65536;
constexpr int KB9   = 9;
constexpr int BATCH = 32;
constexpr int LOUT  = (TFR - 1) * 4;            // 262140

constexpr int OT      = 1000;                    // output samples per tile
constexpr int NT      = (LOUT + OT - 1) / OT;    // 263 tiles
constexpr int NTHR    = 256;
constexpr int MAXNFR  = OT / 4 + 3;              // 253
constexpr int MAXROWS = MAXNFR + 7;              // 260
constexpr int SMC     = 12;                      // sMc row stride (words)
constexpr int SSP     = 20;                      // sspec row stride (words)

// ---------------------------------------------------------------------------
// Compile-time twiddles (all angles multiples of pi/8)
// ---------------------------------------------------------------------------
#define HD __host__ __device__ __forceinline__

HD constexpr float cos8c(int m) {
    m &= 15;
    const int mm = m & 7;
    const float v =
        (mm == 0) ?  1.0f :
        (mm == 1) ?  0.92387953251128674f :
        (mm == 2) ?  0.70710678118654752f :
        (mm == 3) ?  0.38268343236508977f :
        (mm == 4) ?  0.0f :
        (mm == 5) ? -0.38268343236508977f :
        (mm == 6) ? -0.70710678118654752f :
                    -0.92387953251128674f;
    return (m & 8) ? -v : v;
}
HD constexpr float sin8c(int m) { return cos8c(m + 12); }
HD constexpr float wwinc(int n) { return 0.5f - 0.5f * cos8c(n); }   // hann(16), symmetric, w0=0
// Combined-pair ISTFT coefficients (k = 0..4); even n uses sums, odd n uses diffs.
HD constexpr float CSc(int k, int n) { return ((k == 0) ? 1.0f : 2.0f) * 0.0625f * cos8c(k * n) * wwinc(n); }
HD constexpr float SNc(int k, int n) { return -2.0f * 0.0625f * sin8c(k * n) * wwinc(n); }
HD constexpr float envsum(int r) {
    return wwinc(r)      * wwinc(r)      + wwinc(r + 4)  * wwinc(r + 4)
         + wwinc(r + 8)  * wwinc(r + 8)  + wwinc(r + 12) * wwinc(r + 12);
}
constexpr float EINV0 = 1.0f / envsum(0);
constexpr float EINV1 = 1.0f / envsum(1);
constexpr float EINV2 = 1.0f / envsum(2);
constexpr float EINV3 = 1.0f / envsum(3);

// Runtime tables for rare edge-fallback paths
__constant__ float C8T[16] = { cos8c(0), cos8c(1), cos8c(2), cos8c(3), cos8c(4), cos8c(5), cos8c(6), cos8c(7),
                               cos8c(8), cos8c(9), cos8c(10), cos8c(11), cos8c(12), cos8c(13), cos8c(14), cos8c(15) };
__constant__ float S8T[16] = { sin8c(0), sin8c(1), sin8c(2), sin8c(3), sin8c(4), sin8c(5), sin8c(6), sin8c(7),
                               sin8c(8), sin8c(9), sin8c(10), sin8c(11), sin8c(12), sin8c(13), sin8c(14), sin8c(15) };
__constant__ float W16T[16] = { wwinc(0), wwinc(1), wwinc(2), wwinc(3), wwinc(4), wwinc(5), wwinc(6), wwinc(7),
                                wwinc(8), wwinc(9), wwinc(10), wwinc(11), wwinc(12), wwinc(13), wwinc(14), wwinc(15) };

// ---------------------------------------------------------------------------
__global__ void __launch_bounds__(NTHR)
glim_kernel(const float* __restrict__ mag, float* __restrict__ out)
{
    __shared__ __align__(16) float sMc[MAXROWS * SMC];   // [S0..3][D0..3][M4,pad,pad,pad]
    __shared__ __align__(16) float swav[1024];
    __shared__ __align__(16) float sspec[MAXNFR * SSP];  // [Sa0..3][Da0..3][Bs1..3,B4][Bd1..3,a4]

    const int tid  = threadIdx.x;
    const int b    = blockIdx.y;
    const int s0   = blockIdx.x * OT;
    const int nout = min(OT, LOUT - s0);
    const int F0   = s0 >> 2;
    const int TLO  = max(0, F0 - 1);
    const int THI  = min(TFR - 1, (s0 + nout + 7) >> 2);
    const int NFR  = THI - TLO + 1;
    const int tM0  = TLO - 3;
    const int ROWS = NFR + 7;

    const float* magb = mag + (size_t)b * (KB9 * TFR);

    // ---- stage: load bin pairs, store combined S/D + M4 ----
    #pragma unroll
    for (int pass = 0; pass < 2; pass++) {
        const int tt = tid + pass * NTHR;
        if (tt < ROWS) {
            const int tg = tM0 + tt;
            float4 S, D; float m4;
            if (tg >= 0 && tg < TFR) {
                const float* gp = magb + tg;
                const float a0 = __ldg(gp);            const float a8 = __ldg(gp + 8 * TFR);
                const float a1 = __ldg(gp + 1 * TFR);  const float a7 = __ldg(gp + 7 * TFR);
                const float a2 = __ldg(gp + 2 * TFR);  const float a6 = __ldg(gp + 6 * TFR);
                const float a3 = __ldg(gp + 3 * TFR);  const float a5 = __ldg(gp + 5 * TFR);
                m4 = __ldg(gp + 4 * TFR);
                S = make_float4(a0 + a8, a1 + a7, a2 + a6, a3 + a5);
                D = make_float4(a0 - a8, a1 - a7, a2 - a6, a3 - a5);
            } else {
                S = make_float4(0.f, 0.f, 0.f, 0.f);
                D = S; m4 = 0.f;
            }
            float* rp = sMc + tt * SMC;
            *reinterpret_cast<float4*>(rp)     = S;
            *reinterpret_cast<float4*>(rp + 4) = D;
            rp[8] = m4;
        }
    }
    __syncthreads();

    // ---- Phase A: wav_i (ISTFT of zero-phase spectrum) ----
    const int ngA = NFR + 3;
    if (tid < ngA) {
        const int g     = tid;
        const int jbase = 4 * TLO - 8 + 4 * g;
        const int X     = TLO + g;
        if (jbase >= 0 && jbase + 3 < LOUT && X >= 3 && X <= TFR - 1) {
            float y0 = 0.f, y1 = 0.f, y2 = 0.f, y3 = 0.f;
            #pragma unroll
            for (int jj = 0; jj < 4; jj++) {
                const float* rp = sMc + (g + 3 - jj) * SMC;
                const float4 u0 = *reinterpret_cast<const float4*>(rp);
                const float4 u1 = *reinterpret_cast<const float4*>(rp + 4);
                const float  m4 = rp[8];
                // r = 0 (even n)
                { const int n = 4 * jj + 0;
                  if (CSc(0,n) != 0.f) y0 = fmaf(u0.x, CSc(0,n), y0);
                  if (CSc(1,n) != 0.f) y0 = fmaf(u0.y, CSc(1,n), y0);
                  if (CSc(2,n) != 0.f) y0 = fmaf(u0.z, CSc(2,n), y0);
                  if (CSc(3,n) != 0.f) y0 = fmaf(u0.w, CSc(3,n), y0);
                  if (CSc(4,n) != 0.f) y0 = fmaf(m4,   CSc(4,n), y0); }
                // r = 1 (odd n)
                { const int n = 4 * jj + 1;
                  if (CSc(0,n) != 0.f) y1 = fmaf(u1.x, CSc(0,n), y1);
                  if (CSc(1,n) != 0.f) y1 = fmaf(u1.y, CSc(1,n), y1);
                  if (CSc(2,n) != 0.f) y1 = fmaf(u1.z, CSc(2,n), y1);
                  if (CSc(3,n) != 0.f) y1 = fmaf(u1.w, CSc(3,n), y1); }
                // r = 2 (even n)
                { const int n = 4 * jj + 2;
                  if (CSc(0,n) != 0.f) y2 = fmaf(u0.x, CSc(0,n), y2);
                  if (CSc(1,n) != 0.f) y2 = fmaf(u0.y, CSc(1,n), y2);
                  if (CSc(2,n) != 0.f) y2 = fmaf(u0.z, CSc(2,n), y2);
                  if (CSc(3,n) != 0.f) y2 = fmaf(u0.w, CSc(3,n), y2);
                  if (CSc(4,n) != 0.f) y2 = fmaf(m4,   CSc(4,n), y2); }
                // r = 3 (odd n)
                { const int n = 4 * jj + 3;
                  if (CSc(0,n) != 0.f) y3 = fmaf(u1.x, CSc(0,n), y3);
                  if (CSc(1,n) != 0.f) y3 = fmaf(u1.y, CSc(1,n), y3);
                  if (CSc(2,n) != 0.f) y3 = fmaf(u1.z, CSc(2,n), y3);
                  if (CSc(3,n) != 0.f) y3 = fmaf(u1.w, CSc(3,n), y3); }
            }
            *reinterpret_cast<float4*>(swav + 4 * g) =
                make_float4(y0 * EINV0, y1 * EINV1, y2 * EINV2, y3 * EINV3);
        } else {
            // Edge fallback: reflect + clamp + edge env (runtime tables)
            for (int r = 0; r < 4; r++) {
                const int jg = jbase + r;
                const int jr = (jg < 0) ? -jg : ((jg >= LOUT) ? 2 * LOUT - 2 - jg : jg);
                const int p  = jr + 8;
                const int Xp = p >> 2;
                const int rr = p & 3;
                float acc = 0.f, env = 0.f;
                for (int jj = 0; jj < 4; jj++) {
                    const int t = Xp - jj;
                    if (t < 0 || t >= TFR) continue;
                    const int n = rr + 4 * jj;
                    const float w = W16T[n];
                    const float* rp = sMc + (t - tM0) * SMC;
                    float ssum;
                    if (n & 1) {
                        ssum = rp[4]
                             + 2.f * (rp[5] * C8T[n & 15] + rp[6] * C8T[(2 * n) & 15] + rp[7] * C8T[(3 * n) & 15]);
                    } else {
                        ssum = rp[0]
                             + 2.f * (rp[1] * C8T[n & 15] + rp[2] * C8T[(2 * n) & 15] + rp[3] * C8T[(3 * n) & 15]
                                    + rp[8] * C8T[(4 * n) & 15]);
                    }
                    acc = fmaf(ssum, 0.0625f * w, acc);
                    env = fmaf(w, w, env);
                }
                swav[4 * g + r] = acc / env;
            }
        }
    }
    __syncthreads();

    // ---- Phase B1: rfft (symmetry-folded) + phase normalization ----
    if (tid < NFR) {
        const int f = tid;
        const float4* w4 = reinterpret_cast<const float4*>(swav + 4 * f);
        const float4 A0 = w4[0], A1 = w4[1], A2 = w4[2], A3 = w4[3];
        const float x1 = A0.y, x2 = A0.z, x3 = A0.w, x4 = A1.x, x5 = A1.y, x6 = A1.z, x7 = A1.w;
        const float x8 = A2.x, x9 = A2.y, x10 = A2.z, x11 = A2.w, x12 = A3.x, x13 = A3.y, x14 = A3.z, x15 = A3.w;

        float e[8], o[8];
        e[1] = wwinc(1) * (x1 + x15);  o[1] = wwinc(1) * (x1 - x15);
        e[2] = wwinc(2) * (x2 + x14);  o[2] = wwinc(2) * (x2 - x14);
        e[3] = wwinc(3) * (x3 + x13);  o[3] = wwinc(3) * (x3 - x13);
        e[4] = wwinc(4) * (x4 + x12);  o[4] = wwinc(4) * (x4 - x12);
        e[5] = wwinc(5) * (x5 + x11);  o[5] = wwinc(5) * (x5 - x11);
        e[6] = wwinc(6) * (x6 + x10);  o[6] = wwinc(6) * (x6 - x10);
        e[7] = wwinc(7) * (x7 + x9);   o[7] = wwinc(7) * (x7 - x9);

        // magnitudes (L2-hot coalesced reloads)
        const float* mp = magb + (TLO + f);
        float mv[9];
        #pragma unroll
        for (int k = 0; k < 9; k++) mv[k] = __ldg(mp + k * TFR);

        float ca[9], sa[9];
        #pragma unroll
        for (int k = 0; k < 9; k++) {
            float re = (k & 1) ? -x8 : x8;
            #pragma unroll
            for (int n = 1; n < 8; n++) {
                const float c = cos8c(k * n);
                if (c != 0.f) re = fmaf(e[n], c, re);
            }
            if (k == 0 || k == 8) {
                ca[k] = copysignf(mv[k], re);
                sa[k] = 0.f;
            } else {
                float im = 0.f;
                #pragma unroll
                for (int n = 1; n < 8; n++) {
                    const float ns = -sin8c(k * n);
                    if (ns != 0.f) im = fmaf(o[n], ns, im);
                }
                const float n2 = fmaf(re, re, im * im);
                if (n2 > 0.f) {
                    const float u = mv[k] * rsqrtf(n2);
                    ca[k] = re * u;
                    sa[k] = im * u;
                } else {
                    ca[k] = mv[k];
                    sa[k] = 0.f;
                }
            }
        }

        float* rp = sspec + f * SSP;
        *reinterpret_cast<float4*>(rp)      = make_float4(ca[0] + ca[8], ca[1] + ca[7], ca[2] + ca[6], ca[3] + ca[5]);
        *reinterpret_cast<float4*>(rp + 4)  = make_float4(ca[0] - ca[8], ca[1] - ca[7], ca[2] - ca[6], ca[3] - ca[5]);
        *reinterpret_cast<float4*>(rp + 8)  = make_float4(sa[1] + sa[7], sa[2] + sa[6], sa[3] + sa[5], sa[4]);
        *reinterpret_cast<float4*>(rp + 12) = make_float4(sa[1] - sa[7], sa[2] - sa[6], sa[3] - sa[5], ca[4]);
    }
    __syncthreads();

    // ---- Phase B2: final ISTFT + env normalization ----
    const int ngO = nout >> 2;
    float* outb = out + (size_t)b * LOUT + s0;
    if (tid < ngO) {
        const int g = tid;
        const int X = F0 + g + 2;
        if (X - 3 >= TLO && X <= THI) {
            float y0 = 0.f, y1 = 0.f, y2 = 0.f, y3 = 0.f;
            #pragma unroll
            for (int jj = 0; jj < 4; jj++) {
                const float* rp = sspec + (X - jj - TLO) * SSP;
                const float4 v0 = *reinterpret_cast<const float4*>(rp);
                const float4 v1 = *reinterpret_cast<const float4*>(rp + 4);
                const float4 v2 = *reinterpret_cast<const float4*>(rp + 8);
                const float4 v3 = *reinterpret_cast<const float4*>(rp + 12);
                // r = 0 (even n)
                { const int n = 4 * jj + 0;
                  if (CSc(0,n) != 0.f) y0 = fmaf(v0.x, CSc(0,n), y0);
                  if (CSc(1,n) != 0.f) y0 = fmaf(v0.y, CSc(1,n), y0);
                  if (CSc(2,n) != 0.f) y0 = fmaf(v0.z, CSc(2,n), y0);
                  if (CSc(3,n) != 0.f) y0 = fmaf(v0.w, CSc(3,n), y0);
                  if (CSc(4,n) != 0.f) y0 = fmaf(v3.w, CSc(4,n), y0);
                  if (SNc(1,n) != 0.f) y0 = fmaf(v3.x, SNc(1,n), y0);
                  if (SNc(2,n) != 0.f) y0 = fmaf(v3.y, SNc(2,n), y0);
                  if (SNc(3,n) != 0.f) y0 = fmaf(v3.z, SNc(3,n), y0); }
                // r = 1 (odd n)
                { const int n = 4 * jj + 1;
                  if (CSc(0,n) != 0.f) y1 = fmaf(v1.x, CSc(0,n), y1);
                  if (CSc(1,n) != 0.f) y1 = fmaf(v1.y, CSc(1,n), y1);
                  if (CSc(2,n) != 0.f) y1 = fmaf(v1.z, CSc(2,n), y1);
                  if (CSc(3,n) != 0.f) y1 = fmaf(v1.w, CSc(3,n), y1);
                  if (SNc(1,n) != 0.f) y1 = fmaf(v2.x, SNc(1,n), y1);
                  if (SNc(2,n) != 0.f) y1 = fmaf(v2.y, SNc(2,n), y1);
                  if (SNc(3,n) != 0.f) y1 = fmaf(v2.z, SNc(3,n), y1);
                  if (SNc(4,n) != 0.f) y1 = fmaf(v2.w, SNc(4,n), y1); }
                // r = 2 (even n)
                { const int n = 4 * jj + 2;
                  if (CSc(0,n) != 0.f) y2 = fmaf(v0.x, CSc(0,n), y2);
                  if (CSc(1,n) != 0.f) y2 = fmaf(v0.y, CSc(1,n), y2);
                  if (CSc(2,n) != 0.f) y2 = fmaf(v0.z, CSc(2,n), y2);
                  if (CSc(3,n) != 0.f) y2 = fmaf(v0.w, CSc(3,n), y2);
                  if (CSc(4,n) != 0.f) y2 = fmaf(v3.w, CSc(4,n), y2);
                  if (SNc(1,n) != 0.f) y2 = fmaf(v3.x, SNc(1,n), y2);
                  if (SNc(2,n) != 0.f) y2 = fmaf(v3.y, SNc(2,n), y2);
                  if (SNc(3,n) != 0.f) y2 = fmaf(v3.z, SNc(3,n), y2); }
                // r = 3 (odd n)
                { const int n = 4 * jj + 3;
                  if (CSc(0,n) != 0.f) y3 = fmaf(v1.x, CSc(0,n), y3);
                  if (CSc(1,n) != 0.f) y3 = fmaf(v1.y, CSc(1,n), y3);
                  if (CSc(2,n) != 0.f) y3 = fmaf(v1.z, CSc(2,n), y3);
                  if (CSc(3,n) != 0.f) y3 = fmaf(v1.w, CSc(3,n), y3);
                  if (SNc(1,n) != 0.f) y3 = fmaf(v2.x, SNc(1,n), y3);
                  if (SNc(2,n) != 0.f) y3 = fmaf(v2.y, SNc(2,n), y3);
                  if (SNc(3,n) != 0.f) y3 = fmaf(v2.z, SNc(3,n), y3);
                  if (SNc(4,n) != 0.f) y3 = fmaf(v2.w, SNc(4,n), y3); }
            }
            *reinterpret_cast<float4*>(outb + 4 * g) =
                make_float4(y0 * EINV0, y1 * EINV1, y2 * EINV2, y3 * EINV3);
        } else {
            // Boundary fallback (runtime tables, clamped frames, edge env)
            for (int r = 0; r < 4; r++) {
                const int s = s0 + 4 * g + r;
                const int p  = s + 8;
                const int Xp = p >> 2;
                const int rr = p & 3;
                float acc = 0.f, env = 0.f;
                for (int jj = 0; jj < 4; jj++) {
                    const int t = Xp - jj;
                    if (t < TLO || t > THI) continue;
                    const int n = rr + 4 * jj;
                    const float w = W16T[n];
                    const float* rp = sspec + (t - TLO) * SSP;
                    float ssum;
                    if (n & 1) {
                        ssum = rp[4]
                             + 2.f * (rp[5] * C8T[n & 15] + rp[6] * C8T[(2 * n) & 15] + rp[7] * C8T[(3 * n) & 15])
                             - 2.f * (rp[8] * S8T[n & 15] + rp[9] * S8T[(2 * n) & 15] + rp[10] * S8T[(3 * n) & 15]
                                    + rp[11] * S8T[(4 * n) & 15]);
                    } else {
                        ssum = rp[0]
                             + 2.f * (rp[1] * C8T[n & 15] + rp[2] * C8T[(2 * n) & 15] + rp[3] * C8T[(3 * n) & 15]
                                    + rp[15] * C8T[(4 * n) & 15])
                             - 2.f * (rp[12] * S8T[n & 15] + rp[13] * S8T[(2 * n) & 15] + rp[14] * S8T[(3 * n) & 15]);
                    }
                    acc = fmaf(ssum, 0.0625f * w, acc);
                    env = fmaf(w, w, env);
                }
                outb[4 * g + r] = acc / env;
            }
        }
    }
}

// ---------------------------------------------------------------------------
extern "C" void kernel_launch(void* const* d_in, const int* in_sizes, int n_in,
                              void* d_out, int out_size)
{
    (void)in_sizes; (void)n_in; (void)out_size;
    const float* mag = (const float*)d_in[0];
    float* out = (float*)d_out;
    dim3 grid(NT, BATCH);
    glim_kernel<<<grid, NTHR>>>(mag, out);
}

// round 4
// speedup vs baseline: 1.0435x; 1.0435x over previous
#include <cuda_runtime.h>

// ---------------------------------------------------------------------------
// Problem constants
// ---------------------------------------------------------------------------
constexpr int TFR   = 65536;
constexpr int KB9   = 9;
constexpr int BATCH = 32;
constexpr int LOUT  = (TFR - 1) * 4;            // 262140

constexpr int OT   = 1000;                      // output samples per tile
constexpr int NT   = (LOUT + OT - 1) / OT;      // 263 tiles
constexpr int NTHR = 256;

// Shared-memory layout (word offsets). Even/odd row split; the E->O base
// deltas are chosen == 16 (mod 32 words) so mixed-parity warp accesses are
// bank-conflict-free.
constexpr int OFF_MCE = 0;                       // mag rows even: 130 x 12
constexpr int OFF_MCO = 1584;                    // mag rows odd:  130 x 12   (delta 1584 % 32 == 16)
constexpr int OFF_WVE = 3144;                    // wav groups even: 128 x 4
constexpr int OFF_WVO = 3656;                    // wav groups odd:  128 x 4
constexpr int OFF_SPE = 4168;                    // spec rows even: 127 x 20 (+pad)
constexpr int OFF_SPO = 6744;                    // spec rows odd:  126 x 20  (delta 2576 % 32 == 16)
constexpr int SMWORDS = 9280;                    // 37120 bytes

// ---------------------------------------------------------------------------
// Compile-time twiddles (all angles multiples of pi/8)
// ---------------------------------------------------------------------------
#define HD __host__ __device__ __forceinline__

HD constexpr float cos8c(int m) {
    m &= 15;
    const int mm = m & 7;
    const float v =
        (mm == 0) ?  1.0f :
        (mm == 1) ?  0.92387953251128674f :
        (mm == 2) ?  0.70710678118654752f :
        (mm == 3) ?  0.38268343236508977f :
        (mm == 4) ?  0.0f :
        (mm == 5) ? -0.38268343236508977f :
        (mm == 6) ? -0.70710678118654752f :
                    -0.92387953251128674f;
    return (m & 8) ? -v : v;
}
HD constexpr float sin8c(int m) { return cos8c(m + 12); }
HD constexpr float wwinc(int n) { return 0.5f - 0.5f * cos8c(n); }   // hann(16)
HD constexpr float CSc(int k, int n) { return ((k == 0) ? 1.0f : 2.0f) * 0.0625f * cos8c(k * n) * wwinc(n); }
HD constexpr float SNc(int k, int n) { return -2.0f * 0.0625f * sin8c(k * n) * wwinc(n); }
HD constexpr float envsum(int r) {
    return wwinc(r)      * wwinc(r)      + wwinc(r + 4)  * wwinc(r + 4)
         + wwinc(r + 8)  * wwinc(r + 8)  + wwinc(r + 12) * wwinc(r + 12);
}
HD constexpr float EINVc(int r) { return 1.0f / envsum(r); }
// env-folded coefficients for the interior fast paths
HD constexpr float CSF(int k, int n) { return CSc(k, n) * EINVc(n & 3); }
HD constexpr float SNF(int k, int n) { return SNc(k, n) * EINVc(n & 3); }

// Runtime tables for rare edge-fallback paths
__constant__ float C8T[16] = { cos8c(0), cos8c(1), cos8c(2), cos8c(3), cos8c(4), cos8c(5), cos8c(6), cos8c(7),
                               cos8c(8), cos8c(9), cos8c(10), cos8c(11), cos8c(12), cos8c(13), cos8c(14), cos8c(15) };
__constant__ float S8T[16] = { sin8c(0), sin8c(1), sin8c(2), sin8c(3), sin8c(4), sin8c(5), sin8c(6), sin8c(7),
                               sin8c(8), sin8c(9), sin8c(10), sin8c(11), sin8c(12), sin8c(13), sin8c(14), sin8c(15) };
__constant__ float W16T[16] = { wwinc(0), wwinc(1), wwinc(2), wwinc(3), wwinc(4), wwinc(5), wwinc(6), wwinc(7),
                                wwinc(8), wwinc(9), wwinc(10), wwinc(11), wwinc(12), wwinc(13), wwinc(14), wwinc(15) };

// ---------------------------------------------------------------------------
// Row-pointer helpers (even/odd split)
// ---------------------------------------------------------------------------
__device__ __forceinline__ float* magRowPtr(float* sm, int r) {
    return sm + (r >> 1) * 12 + ((r & 1) ? OFF_MCO : OFF_MCE);
}
__device__ __forceinline__ float* specRowPtr(float* sm, int r) {
    return sm + (r >> 1) * 20 + ((r & 1) ? OFF_SPO : OFF_SPE);
}
__device__ __forceinline__ float* wavPtr(float* sm, int g) {
    return sm + (g >> 1) * 4 + ((g & 1) ? OFF_WVO : OFF_WVE);
}

// ---------------------------------------------------------------------------
// Per-row accumulators (fully constant-folded; env folded into coefficients)
// ---------------------------------------------------------------------------
template<int JJ>
__device__ __forceinline__ void accA(const float4 u0, const float4 u1, const float m4,
                                     float& y0, float& y1, float& y2, float& y3)
{
    { constexpr int n = 4 * JJ + 0;
      if (CSF(0,n) != 0.f) y0 = fmaf(u0.x, CSF(0,n), y0);
      if (CSF(1,n) != 0.f) y0 = fmaf(u0.y, CSF(1,n), y0);
      if (CSF(2,n) != 0.f) y0 = fmaf(u0.z, CSF(2,n), y0);
      if (CSF(3,n) != 0.f) y0 = fmaf(u0.w, CSF(3,n), y0);
      if (CSF(4,n) != 0.f) y0 = fmaf(m4,   CSF(4,n), y0); }
    { constexpr int n = 4 * JJ + 1;
      if (CSF(0,n) != 0.f) y1 = fmaf(u1.x, CSF(0,n), y1);
      if (CSF(1,n) != 0.f) y1 = fmaf(u1.y, CSF(1,n), y1);
      if (CSF(2,n) != 0.f) y1 = fmaf(u1.z, CSF(2,n), y1);
      if (CSF(3,n) != 0.f) y1 = fmaf(u1.w, CSF(3,n), y1); }
    { constexpr int n = 4 * JJ + 2;
      if (CSF(0,n) != 0.f) y2 = fmaf(u0.x, CSF(0,n), y2);
      if (CSF(1,n) != 0.f) y2 = fmaf(u0.y, CSF(1,n), y2);
      if (CSF(2,n) != 0.f) y2 = fmaf(u0.z, CSF(2,n), y2);
      if (CSF(3,n) != 0.f) y2 = fmaf(u0.w, CSF(3,n), y2);
      if (CSF(4,n) != 0.f) y2 = fmaf(m4,   CSF(4,n), y2); }
    { constexpr int n = 4 * JJ + 3;
      if (CSF(0,n) != 0.f) y3 = fmaf(u1.x, CSF(0,n), y3);
      if (CSF(1,n) != 0.f) y3 = fmaf(u1.y, CSF(1,n), y3);
      if (CSF(2,n) != 0.f) y3 = fmaf(u1.z, CSF(2,n), y3);
      if (CSF(3,n) != 0.f) y3 = fmaf(u1.w, CSF(3,n), y3); }
}

template<int JJ>
__device__ __forceinline__ void accB(const float4 v0, const float4 v1, const float4 v2, const float4 v3,
                                     float& y0, float& y1, float& y2, float& y3)
{
    { constexpr int n = 4 * JJ + 0;
      if (CSF(0,n) != 0.f) y0 = fmaf(v0.x, CSF(0,n), y0);
      if (CSF(1,n) != 0.f) y0 = fmaf(v0.y, CSF(1,n), y0);
      if (CSF(2,n) != 0.f) y0 = fmaf(v0.z, CSF(2,n), y0);
      if (CSF(3,n) != 0.f) y0 = fmaf(v0.w, CSF(3,n), y0);
      if (CSF(4,n) != 0.f) y0 = fmaf(v3.w, CSF(4,n), y0);
      if (SNF(1,n) != 0.f) y0 = fmaf(v3.x, SNF(1,n), y0);
      if (SNF(2,n) != 0.f) y0 = fmaf(v3.y, SNF(2,n), y0);
      if (SNF(3,n) != 0.f) y0 = fmaf(v3.z, SNF(3,n), y0); }
    { constexpr int n = 4 * JJ + 1;
      if (CSF(0,n) != 0.f) y1 = fmaf(v1.x, CSF(0,n), y1);
      if (CSF(1,n) != 0.f) y1 = fmaf(v1.y, CSF(1,n), y1);
      if (CSF(2,n) != 0.f) y1 = fmaf(v1.z, CSF(2,n), y1);
      if (CSF(3,n) != 0.f) y1 = fmaf(v1.w, CSF(3,n), y1);
      if (SNF(1,n) != 0.f) y1 = fmaf(v2.x, SNF(1,n), y1);
      if (SNF(2,n) != 0.f) y1 = fmaf(v2.y, SNF(2,n), y1);
      if (SNF(3,n) != 0.f) y1 = fmaf(v2.z, SNF(3,n), y1);
      if (SNF(4,n) != 0.f) y1 = fmaf(v2.w, SNF(4,n), y1); }
    { constexpr int n = 4 * JJ + 2;
      if (CSF(0,n) != 0.f) y2 = fmaf(v0.x, CSF(0,n), y2);
      if (CSF(1,n) != 0.f) y2 = fmaf(v0.y, CSF(1,n), y2);
      if (CSF(2,n) != 0.f) y2 = fmaf(v0.z, CSF(2,n), y2);
      if (CSF(3,n) != 0.f) y2 = fmaf(v0.w, CSF(3,n), y2);
      if (CSF(4,n) != 0.f) y2 = fmaf(v3.w, CSF(4,n), y2);
      if (SNF(1,n) != 0.f) y2 = fmaf(v3.x, SNF(1,n), y2);
      if (SNF(2,n) != 0.f) y2 = fmaf(v3.y, SNF(2,n), y2);
      if (SNF(3,n) != 0.f) y2 = fmaf(v3.z, SNF(3,n), y2); }
    { constexpr int n = 4 * JJ + 3;
      if (CSF(0,n) != 0.f) y3 = fmaf(v1.x, CSF(0,n), y3);
      if (CSF(1,n) != 0.f) y3 = fmaf(v1.y, CSF(1,n), y3);
      if (CSF(2,n) != 0.f) y3 = fmaf(v1.z, CSF(2,n), y3);
      if (CSF(3,n) != 0.f) y3 = fmaf(v1.w, CSF(3,n), y3);
      if (SNF(1,n) != 0.f) y3 = fmaf(v2.x, SNF(1,n), y3);
      if (SNF(2,n) != 0.f) y3 = fmaf(v2.y, SNF(2,n), y3);
      if (SNF(3,n) != 0.f) y3 = fmaf(v2.z, SNF(3,n), y3);
      if (SNF(4,n) != 0.f) y3 = fmaf(v2.w, SNF(4,n), y3); }
}

// ---------------------------------------------------------------------------
__global__ void __launch_bounds__(NTHR)
glim_kernel(const float* __restrict__ mag, float* __restrict__ out)
{
    __shared__ __align__(16) float sm[SMWORDS];

    const int tid  = threadIdx.x;
    const int b    = blockIdx.y;
    const int s0   = blockIdx.x * OT;
    const int nout = min(OT, LOUT - s0);
    const int F0   = s0 >> 2;
    const int TLO  = max(0, F0 - 1);
    const int THI  = min(TFR - 1, (s0 + nout + 7) >> 2);
    const int NFR  = THI - TLO + 1;
    const int tM0  = TLO - 3;
    const int ROWS = NFR + 7;

    const float* magb = mag + (size_t)b * (KB9 * TFR);

    // ---- stage: load bin pairs, store combined S/D + M4 ----
    #pragma unroll
    for (int pass = 0; pass < 2; pass++) {
        const int tt = tid + pass * NTHR;
        if (tt < ROWS) {
            const int tg = tM0 + tt;
            float4 S, D; float m4;
            if (tg >= 0 && tg < TFR) {
                const float* gp = magb + tg;
                const float a0 = __ldg(gp);            const float a8 = __ldg(gp + 8 * TFR);
                const float a1 = __ldg(gp + 1 * TFR);  const float a7 = __ldg(gp + 7 * TFR);
                const float a2 = __ldg(gp + 2 * TFR);  const float a6 = __ldg(gp + 6 * TFR);
                const float a3 = __ldg(gp + 3 * TFR);  const float a5 = __ldg(gp + 5 * TFR);
                m4 = __ldg(gp + 4 * TFR);
                S = make_float4(a0 + a8, a1 + a7, a2 + a6, a3 + a5);
                D = make_float4(a0 - a8, a1 - a7, a2 - a6, a3 - a5);
            } else {
                S = make_float4(0.f, 0.f, 0.f, 0.f);
                D = S; m4 = 0.f;
            }
            float* rp = magRowPtr(sm, tt);
            *reinterpret_cast<float4*>(rp)     = S;
            *reinterpret_cast<float4*>(rp + 4) = D;
            rp[8] = m4;
        }
    }
    __syncthreads();

    // ---- Phase A (paired): wav_i = ISTFT of zero-phase spectrum ----
    const int ngA = NFR + 3;
    const int npA = (ngA + 1) >> 1;
    if (tid < npA) {
        const int t  = tid;
        const int g0 = 2 * t;
        const int g1 = g0 + 1;
        const int jb0 = 4 * TLO - 8 + 4 * g0;
        const int X0  = TLO + g0;
        const bool fast = (g1 < ngA) && (jb0 >= 0) && (jb0 + 7 < LOUT) &&
                          (X0 >= 3) && (X0 + 1 <= TFR - 1);
        if (fast) {
            float y00 = 0.f, y01 = 0.f, y02 = 0.f, y03 = 0.f;
            float y10 = 0.f, y11 = 0.f, y12 = 0.f, y13 = 0.f;
            const float* rE = sm + OFF_MCE + t * 12;   // rows 2t, 2t+2, 2t+4
            const float* rO = sm + OFF_MCO + t * 12;   // rows 2t+1, 2t+3
            {   // d=0: row 2t  -> g0 jj=3
                const float4 u0 = *reinterpret_cast<const float4*>(rE);
                const float4 u1 = *reinterpret_cast<const float4*>(rE + 4);
                const float  m4 = rE[8];
                accA<3>(u0, u1, m4, y00, y01, y02, y03);
            }
            {   // d=1: row 2t+1 -> g0 jj=2, g1 jj=3
                const float4 u0 = *reinterpret_cast<const float4*>(rO);
                const float4 u1 = *reinterpret_cast<const float4*>(rO + 4);
                const float  m4 = rO[8];
                accA<2>(u0, u1, m4, y00, y01, y02, y03);
                accA<3>(u0, u1, m4, y10, y11, y12, y13);
            }
            {   // d=2: row 2t+2 -> g0 jj=1, g1 jj=2
                const float4 u0 = *reinterpret_cast<const float4*>(rE + 12);
                const float4 u1 = *reinterpret_cast<const float4*>(rE + 16);
                const float  m4 = rE[20];
                accA<1>(u0, u1, m4, y00, y01, y02, y03);
                accA<2>(u0, u1, m4, y10, y11, y12, y13);
            }
            {   // d=3: row 2t+3 -> g0 jj=0, g1 jj=1
                const float4 u0 = *reinterpret_cast<const float4*>(rO + 12);
                const float4 u1 = *reinterpret_cast<const float4*>(rO + 16);
                const float  m4 = rO[20];
                accA<0>(u0, u1, m4, y00, y01, y02, y03);
                accA<1>(u0, u1, m4, y10, y11, y12, y13);
            }
            {   // d=4: row 2t+4 -> g1 jj=0
                const float4 u0 = *reinterpret_cast<const float4*>(rE + 24);
                const float4 u1 = *reinterpret_cast<const float4*>(rE + 28);
                const float  m4 = rE[32];
                accA<0>(u0, u1, m4, y10, y11, y12, y13);
            }
            *reinterpret_cast<float4*>(sm + OFF_WVE + t * 4) = make_float4(y00, y01, y02, y03);
            *reinterpret_cast<float4*>(sm + OFF_WVO + t * 4) = make_float4(y10, y11, y12, y13);
        } else {
            // Edge fallback: reflect + clamp + edge env (runtime tables)
            for (int gi = 0; gi < 2; gi++) {
                const int g = g0 + gi;
                if (g >= ngA) break;
                const int jbase = 4 * TLO - 8 + 4 * g;
                float* wp = wavPtr(sm, g);
                for (int r = 0; r < 4; r++) {
                    const int jg = jbase + r;
                    const int jr = (jg < 0) ? -jg : ((jg >= LOUT) ? 2 * LOUT - 2 - jg : jg);
                    const int p  = jr + 8;
                    const int Xp = p >> 2;
                    const int rr = p & 3;
                    float acc = 0.f, env = 0.f;
                    for (int jj = 0; jj < 4; jj++) {
                        const int tt = Xp - jj;
                        if (tt < 0 || tt >= TFR) continue;
                        const int n = rr + 4 * jj;
                        const float w = W16T[n];
                        const float* rp = magRowPtr(sm, tt - tM0);
                        float ssum;
                        if (n & 1) {
                            ssum = rp[4]
                                 + 2.f * (rp[5] * C8T[n & 15] + rp[6] * C8T[(2 * n) & 15] + rp[7] * C8T[(3 * n) & 15]);
                        } else {
                            ssum = rp[0]
                                 + 2.f * (rp[1] * C8T[n & 15] + rp[2] * C8T[(2 * n) & 15] + rp[3] * C8T[(3 * n) & 15]
                                        + rp[8] * C8T[(4 * n) & 15]);
                        }
                        acc = fmaf(ssum, 0.0625f * w, acc);
                        env = fmaf(w, w, env);
                    }
                    wp[r] = acc / env;
                }
            }
        }
    }
    __syncthreads();

    // ---- Phase B1: rfft (symmetry-folded) + phase normalization ----
    if (tid < NFR) {
        const int f = tid;
        const int h = f >> 1;
        const float4 *p0, *p1, *p2, *p3;
        if (f & 1) {
            p0 = reinterpret_cast<const float4*>(sm + OFF_WVO + h * 4);
            p1 = reinterpret_cast<const float4*>(sm + OFF_WVE + (h + 1) * 4);
            p2 = reinterpret_cast<const float4*>(sm + OFF_WVO + (h + 1) * 4);
            p3 = reinterpret_cast<const float4*>(sm + OFF_WVE + (h + 2) * 4);
        } else {
            p0 = reinterpret_cast<const float4*>(sm + OFF_WVE + h * 4);
            p1 = reinterpret_cast<const float4*>(sm + OFF_WVO + h * 4);
            p2 = reinterpret_cast<const float4*>(sm + OFF_WVE + (h + 1) * 4);
            p3 = reinterpret_cast<const float4*>(sm + OFF_WVO + (h + 1) * 4);
        }
        const float4 A0 = *p0, A1 = *p1, A2 = *p2, A3 = *p3;
        const float x1 = A0.y, x2 = A0.z, x3 = A0.w, x4 = A1.x, x5 = A1.y, x6 = A1.z, x7 = A1.w;
        const float x8 = A2.x, x9 = A2.y, x10 = A2.z, x11 = A2.w, x12 = A3.x, x13 = A3.y, x14 = A3.z, x15 = A3.w;

        float e[8], o[8];
        e[1] = wwinc(1) * (x1 + x15);  o[1] = wwinc(1) * (x1 - x15);
        e[2] = wwinc(2) * (x2 + x14);  o[2] = wwinc(2) * (x2 - x14);
        e[3] = wwinc(3) * (x3 + x13);  o[3] = wwinc(3) * (x3 - x13);
        e[4] = wwinc(4) * (x4 + x12);  o[4] = wwinc(4) * (x4 - x12);
        e[5] = wwinc(5) * (x5 + x11);  o[5] = wwinc(5) * (x5 - x11);
        e[6] = wwinc(6) * (x6 + x10);  o[6] = wwinc(6) * (x6 - x10);
        e[7] = wwinc(7) * (x7 + x9);   o[7] = wwinc(7) * (x7 - x9);

        // Magnitudes reconstructed from staged S/D (no global reloads)
        const float* mrp = magRowPtr(sm, f + 3);
        const float4 MS = *reinterpret_cast<const float4*>(mrp);
        const float4 MD = *reinterpret_cast<const float4*>(mrp + 4);
        float mv[9];
        mv[0] = 0.5f * (MS.x + MD.x);  mv[8] = 0.5f * (MS.x - MD.x);
        mv[1] = 0.5f * (MS.y + MD.y);  mv[7] = 0.5f * (MS.y - MD.y);
        mv[2] = 0.5f * (MS.z + MD.z);  mv[6] = 0.5f * (MS.z - MD.z);
        mv[3] = 0.5f * (MS.w + MD.w);  mv[5] = 0.5f * (MS.w - MD.w);
        mv[4] = mrp[8];

        float ca[9], sa[9];
        #pragma unroll
        for (int k = 0; k < 9; k++) {
            float re = (k & 1) ? -x8 : x8;
            #pragma unroll
            for (int n = 1; n < 8; n++) {
                const float c = cos8c(k * n);
                if (c != 0.f) re = fmaf(e[n], c, re);
            }
            if (k == 0 || k == 8) {
                ca[k] = copysignf(mv[k], re);
                sa[k] = 0.f;
            } else {
                float im = 0.f;
                #pragma unroll
                for (int n = 1; n < 8; n++) {
                    const float ns = -sin8c(k * n);
                    if (ns != 0.f) im = fmaf(o[n], ns, im);
                }
                const float n2 = fmaf(re, re, im * im);
                if (n2 > 0.f) {
                    const float u = mv[k] * rsqrtf(n2);
                    ca[k] = re * u;
                    sa[k] = im * u;
                } else {
                    ca[k] = mv[k];
                    sa[k] = 0.f;
                }
            }
        }

        float* rp = specRowPtr(sm, f);
        *reinterpret_cast<float4*>(rp)      = make_float4(ca[0] + ca[8], ca[1] + ca[7], ca[2] + ca[6], ca[3] + ca[5]);
        *reinterpret_cast<float4*>(rp + 4)  = make_float4(ca[0] - ca[8], ca[1] - ca[7], ca[2] - ca[6], ca[3] - ca[5]);
        *reinterpret_cast<float4*>(rp + 8)  = make_float4(sa[1] + sa[7], sa[2] + sa[6], sa[3] + sa[5], sa[4]);
        *reinterpret_cast<float4*>(rp + 12) = make_float4(sa[1] - sa[7], sa[2] - sa[6], sa[3] - sa[5], ca[4]);
    }
    __syncthreads();

    // ---- Phase B2 (paired): final ISTFT + env normalization ----
    const int ngO = nout >> 2;
    const int npO = (ngO + 1) >> 1;
    float* outb = out + (size_t)b * LOUT + s0;
    if (tid < npO) {
        const int t  = tid;
        const int g0 = 2 * t;
        const int g1 = g0 + 1;
        const int X0 = F0 + g0 + 2;
        const bool fast = (g1 < ngO) && (X0 - 3 >= TLO) && (X0 + 1 <= THI);
        if (fast) {
            const int Rb = X0 - TLO - 3;     // rows Rb..Rb+4 (parity warp-uniform)
            float y00 = 0.f, y01 = 0.f, y02 = 0.f, y03 = 0.f;
            float y10 = 0.f, y11 = 0.f, y12 = 0.f, y13 = 0.f;
            #define LDSPEC(RP) \
                const float4 v0 = *reinterpret_cast<const float4*>(RP); \
                const float4 v1 = *reinterpret_cast<const float4*>((RP) + 4); \
                const float4 v2 = *reinterpret_cast<const float4*>((RP) + 8); \
                const float4 v3 = *reinterpret_cast<const float4*>((RP) + 12);
            { const float* rp = specRowPtr(sm, Rb);     LDSPEC(rp);
              accB<3>(v0, v1, v2, v3, y00, y01, y02, y03); }
            { const float* rp = specRowPtr(sm, Rb + 1); LDSPEC(rp);
              accB<2>(v0, v1, v2, v3, y00, y01, y02, y03);
              accB<3>(v0, v1, v2, v3, y10, y11, y12, y13); }
            { const float* rp = specRowPtr(sm, Rb + 2); LDSPEC(rp);
              accB<1>(v0, v1, v2, v3, y00, y01, y02, y03);
              accB<2>(v0, v1, v2, v3, y10, y11, y12, y13); }
            { const float* rp = specRowPtr(sm, Rb + 3); LDSPEC(rp);
              accB<0>(v0, v1, v2, v3, y00, y01, y02, y03);
              accB<1>(v0, v1, v2, v3, y10, y11, y12, y13); }
            { const float* rp = specRowPtr(sm, Rb + 4); LDSPEC(rp);
              accB<0>(v0, v1, v2, v3, y10, y11, y12, y13); }
            #undef LDSPEC
            float4* op = reinterpret_cast<float4*>(outb + 8 * t);
            op[0] = make_float4(y00, y01, y02, y03);
            op[1] = make_float4(y10, y11, y12, y13);
        } else {
            // Boundary fallback (runtime tables, clamped frames, edge env)
            for (int gi = 0; gi < 2; gi++) {
                const int g = g0 + gi;
                if (g >= ngO) break;
                for (int r = 0; r < 4; r++) {
                    const int s  = s0 + 4 * g + r;
                    const int p  = s + 8;
                    const int Xp = p >> 2;
                    const int rr = p & 3;
                    float acc = 0.f, env = 0.f;
                    for (int jj = 0; jj < 4; jj++) {
                        const int tt = Xp - jj;
                        if (tt < TLO || tt > THI) continue;
                        const int n = rr + 4 * jj;
                        const float w = W16T[n];
                        const float* rp = specRowPtr(sm, tt - TLO);
                        float ssum;
                        if (n & 1) {
                            ssum = rp[4]
                                 + 2.f * (rp[5] * C8T[n & 15] + rp[6] * C8T[(2 * n) & 15] + rp[7] * C8T[(3 * n) & 15])
                                 - 2.f * (rp[8] * S8T[n & 15] + rp[9] * S8T[(2 * n) & 15] + rp[10] * S8T[(3 * n) & 15]
                                        + rp[11] * S8T[(4 * n) & 15]);
                        } else {
                            ssum = rp[0]
                                 + 2.f * (rp[1] * C8T[n & 15] + rp[2] * C8T[(2 * n) & 15] + rp[3] * C8T[(3 * n) & 15]
                                        + rp[15] * C8T[(4 * n) & 15])
                                 - 2.f * (rp[12] * S8T[n & 15] + rp[13] * S8T[(2 * n) & 15] + rp[14] * S8T[(3 * n) & 15]);
                        }
                        acc = fmaf(ssum, 0.0625f * w, acc);
                        env = fmaf(w, w, env);
                    }
                    outb[4 * g + r] = acc / env;
                }
            }
        }
    }
}

// ---------------------------------------------------------------------------
extern "C" void kernel_launch(void* const* d_in, const int* in_sizes, int n_in,
                              void* d_out, int out_size)
{
    (void)in_sizes; (void)n_in; (void)out_size;
    const float* mag = (const float*)d_in[0];
    float* out = (float*)d_out;
    dim3 grid(NT, BATCH);
    glim_kernel<<<grid, NTHR>>>(mag, out);
}